// round 1
// baseline (speedup 1.0000x reference)
#include <cuda_runtime.h>
#include <cstddef>

#define B 16
#define S 1024
#define D 384
#define QK 64

__device__ float g_Q[(size_t)B * S * QK];
__device__ float g_K[(size_t)B * S * QK];

// ---------------------------------------------------------------------------
// Kernel 1: per-position Q/K projection.
// q[b,n,d] = scale * (sum_c x[b,n,c]*qw[n,d,c] + qb[n,d])
// k[b,n,d] =          sum_c x[b,n,c]*kw[n,d,c]
// One block per n. smem holds x[:,n,:] (16x384). Each lane owns (b, d) pairs;
// full dot per lane -> no reductions. Weights streamed once per n.
// ---------------------------------------------------------------------------
__global__ __launch_bounds__(256) void proj_kernel(
    const float* __restrict__ x, const float* __restrict__ qw,
    const float* __restrict__ qb, const float* __restrict__ kw)
{
    const int n = blockIdx.x;
    __shared__ float xs[B][D + 1];   // +1 pad: bank = (b + c) % 32 -> conflict-free

    const int tid = threadIdx.x;
    for (int idx = tid; idx < B * D; idx += 256) {
        int b = idx / D, c = idx % D;
        xs[b][c] = x[((size_t)b * S + n) * D + c];
    }
    __syncthreads();

    const int lane = tid & 31;
    const int wid  = tid >> 5;
    const int b    = lane & 15;
    const int half = lane >> 4;
    const float scale = 0.05103103630798287f;  // 384^-0.5

    #pragma unroll
    for (int s = 0; s < 8; s++) {
        const int gidx = (wid * 8 + s) * 2 + half;   // 0..127, uniform q/k per warp
        const bool isq = (gidx < 64);
        const int d = isq ? gidx : gidx - 64;
        const float* w = isq ? qw : kw;
        const float4* wp = (const float4*)(w + ((size_t)n * QK + d) * D);

        float a0 = 0.f, a1 = 0.f, a2 = 0.f, a3 = 0.f;
        #pragma unroll 8
        for (int c4 = 0; c4 < D / 4; c4++) {
            float4 wv = __ldg(wp + c4);
            int c = c4 * 4;
            a0 += xs[b][c + 0] * wv.x;
            a1 += xs[b][c + 1] * wv.y;
            a2 += xs[b][c + 2] * wv.z;
            a3 += xs[b][c + 3] * wv.w;
        }
        float acc = (a0 + a1) + (a2 + a3);

        if (isq) {
            g_Q[((size_t)b * S + n) * QK + d] = scale * (acc + qb[n * QK + d]);
        } else {
            g_K[((size_t)b * S + n) * QK + d] = acc;
        }
    }
}

// ---------------------------------------------------------------------------
// Kernel 2: logits[b,n,m] = sum_d q[b,n,d]*k[b,m,d] + attn_bias[n,m]
// 64x64 output tile per block, K=64 fully resident. Tiles stored k-major
// (transposed) in smem so both operands are contiguous float4 reads.
// ---------------------------------------------------------------------------
__global__ __launch_bounds__(256) void logits_kernel(
    const float* __restrict__ attn_bias, float* __restrict__ attn)
{
    const int b  = blockIdx.z;
    const int n0 = blockIdx.y * 64;
    const int m0 = blockIdx.x * 64;

    __shared__ float Qs[QK][68];   // Qs[kk][row]
    __shared__ float Ks[QK][68];   // Ks[kk][col]

    const int tid = threadIdx.x;
    for (int idx = tid; idx < 64 * QK; idx += 256) {
        int r = idx >> 6, kk = idx & 63;
        Qs[kk][r] = g_Q[((size_t)b * S + n0 + r) * QK + kk];
        Ks[kk][r] = g_K[((size_t)b * S + m0 + r) * QK + kk];
    }
    __syncthreads();

    const int tx = tid & 15, ty = tid >> 4;
    float acc[4][4] = {};

    #pragma unroll 16
    for (int kk = 0; kk < QK; kk++) {
        float4 a  = *(const float4*)&Qs[kk][ty * 4];
        float4 bb = *(const float4*)&Ks[kk][tx * 4];
        float av[4] = {a.x, a.y, a.z, a.w};
        float bv[4] = {bb.x, bb.y, bb.z, bb.w};
        #pragma unroll
        for (int i = 0; i < 4; i++)
            #pragma unroll
            for (int j = 0; j < 4; j++)
                acc[i][j] += av[i] * bv[j];
    }

    #pragma unroll
    for (int i = 0; i < 4; i++) {
        const int row = n0 + ty * 4 + i;
        float4 bias4 = *(const float4*)&attn_bias[(size_t)row * S + m0 + tx * 4];
        float4 v = {acc[i][0] + bias4.x, acc[i][1] + bias4.y,
                    acc[i][2] + bias4.z, acc[i][3] + bias4.w};
        *(float4*)&attn[((size_t)b * S + row) * S + m0 + tx * 4] = v;
    }
}

// ---------------------------------------------------------------------------
// Kernel 3: in-place row softmax over 1024 logits. One block per (b,n) row.
// ---------------------------------------------------------------------------
__global__ __launch_bounds__(256) void softmax_kernel(float* __restrict__ attn)
{
    float4* p = (float4*)(attn + (size_t)blockIdx.x * S);
    const int tid = threadIdx.x;
    const int lane = tid & 31, w = tid >> 5;

    float4 v = p[tid];
    float m = fmaxf(fmaxf(v.x, v.y), fmaxf(v.z, v.w));
    #pragma unroll
    for (int o = 16; o > 0; o >>= 1) m = fmaxf(m, __shfl_xor_sync(0xffffffffu, m, o));

    __shared__ float redm[8];
    __shared__ float reds[8];
    if (lane == 0) redm[w] = m;
    __syncthreads();
    m = redm[0];
    #pragma unroll
    for (int i = 1; i < 8; i++) m = fmaxf(m, redm[i]);

    float e0 = expf(v.x - m), e1 = expf(v.y - m);
    float e2 = expf(v.z - m), e3 = expf(v.w - m);
    float ssum = (e0 + e1) + (e2 + e3);
    #pragma unroll
    for (int o = 16; o > 0; o >>= 1) ssum += __shfl_xor_sync(0xffffffffu, ssum, o);
    if (lane == 0) reds[w] = ssum;
    __syncthreads();
    ssum = reds[0];
    #pragma unroll
    for (int i = 1; i < 8; i++) ssum += reds[i];

    const float inv = 1.0f / ssum;
    float4 o4 = {e0 * inv, e1 * inv, e2 * inv, e3 * inv};
    p[tid] = o4;
}

// ---------------------------------------------------------------------------
// Kernel 4: out[b,n,c] = sum_m attn[b,n,m] * x[b,m,c]
// 64x64 tile per block, 16 k-tiles of 64 over m. Same 4x4 microtile scheme.
// ---------------------------------------------------------------------------
__global__ __launch_bounds__(256) void out_kernel(
    const float* __restrict__ x, const float* __restrict__ attn,
    float* __restrict__ out)
{
    const int b  = blockIdx.z;
    const int n0 = blockIdx.y * 64;
    const int c0 = blockIdx.x * 64;

    __shared__ float As[64][68];   // As[kk][row]  (kk = m within tile)
    __shared__ float Xs[64][68];   // Xs[kk][col]

    const int tid = threadIdx.x;
    const int tx = tid & 15, ty = tid >> 4;
    float acc[4][4] = {};

    for (int mt = 0; mt < S / 64; mt++) {
        const int m0 = mt * 64;
        for (int idx = tid; idx < 64 * 64; idx += 256) {
            int r = idx >> 6, kk = idx & 63;
            As[kk][r] = attn[((size_t)b * S + n0 + r) * S + m0 + kk];
            Xs[r][kk] = x[((size_t)b * S + m0 + r) * D + c0 + kk];
        }
        __syncthreads();

        #pragma unroll 16
        for (int kk = 0; kk < 64; kk++) {
            float4 a  = *(const float4*)&As[kk][ty * 4];
            float4 bb = *(const float4*)&Xs[kk][tx * 4];
            float av[4] = {a.x, a.y, a.z, a.w};
            float bv[4] = {bb.x, bb.y, bb.z, bb.w};
            #pragma unroll
            for (int i = 0; i < 4; i++)
                #pragma unroll
                for (int j = 0; j < 4; j++)
                    acc[i][j] += av[i] * bv[j];
        }
        __syncthreads();
    }

    #pragma unroll
    for (int i = 0; i < 4; i++) {
        const int row = n0 + ty * 4 + i;
        float4 v = {acc[i][0], acc[i][1], acc[i][2], acc[i][3]};
        *(float4*)&out[((size_t)b * S + row) * D + c0 + tx * 4] = v;
    }
}

// ---------------------------------------------------------------------------
extern "C" void kernel_launch(void* const* d_in, const int* in_sizes, int n_in,
                              void* d_out, int out_size)
{
    const float* x         = (const float*)d_in[0];
    const float* q_weight  = (const float*)d_in[1];
    const float* q_bias    = (const float*)d_in[2];
    const float* k_weight  = (const float*)d_in[3];
    const float* attn_bias = (const float*)d_in[4];

    float* out  = (float*)d_out;                       // [B,S,D]
    float* attn = (float*)d_out + (size_t)B * S * D;   // [B,S,S]

    proj_kernel<<<S, 256>>>(x, q_weight, q_bias, k_weight);

    dim3 g2(S / 64, S / 64, B);
    logits_kernel<<<g2, 256>>>(attn_bias, attn);

    softmax_kernel<<<B * S, 256>>>(attn);

    dim3 g4(D / 64, S / 64, B);
    out_kernel<<<g4, 256>>>(x, attn, out);
}